// round 5
// baseline (speedup 1.0000x reference)
#include <cuda_runtime.h>
#include <cuda_fp16.h>

#define NMAX 20000
#define EMAX 320000

__device__ float  g_X[NMAX * 512];       // fp32 X[n][h*128+o]
__device__ __half g_Xh[NMAX * 512];      // fp16 copy for gathers
__device__ float  g_sprm[NMAX * 8];      // [n*8+h]=s_src, [n*8+4+h]=s_dst
__device__ float  g_sc[EMAX * 4];        // exp(score), slot-major float4
__device__ int2   g_perm[EMAX];          // sorted-by-src {src, dst}
__device__ int    g_cnt[NMAX];           // histogram / cursor
__device__ int    g_start[NMAX + 1];     // bucket starts
__device__ float  g_hsum[4];
__device__ int    g_is64;

// ---------------------------------------------------------------------------
__global__ void k0_detect(const unsigned int* e32) {
    if (blockIdx.x == 0 && threadIdx.x == 0) {
        int is64 = 1;
        #pragma unroll 1
        for (int i = 0; i < 32; i++) {
            if (e32[2 * i + 1] != 0u) { is64 = 0; break; }
        }
        g_is64 = is64;
    }
}

__device__ __forceinline__ void load_edge(const void* edges, int e, int is64,
                                          int& src, int& dst) {
    if (is64) {
        const long long* p = (const long long*)edges;
        src = (int)p[3 * e];
        dst = (int)p[3 * e + 2];
    } else {
        const int* p = (const int*)edges;
        src = p[3 * e];
        dst = p[3 * e + 2];
    }
}

// ---------------------------------------------------------------------------
__global__ void kzero(int N) {
    int i = blockIdx.x * blockDim.x + threadIdx.x;
    if (i < N) g_cnt[i] = 0;
    if (i < 4) g_hsum[i] = 0.f;
}

__global__ void ksortA(const void* __restrict__ edges, int E) {
    int e = blockIdx.x * blockDim.x + threadIdx.x;
    if (e >= E) return;
    int src, dst;
    load_edge(edges, e, g_is64, src, dst);
    atomicAdd(&g_cnt[src], 1);
}

// single-block exclusive scan over N counters -> g_start (+ copy to g_cnt as cursor)
__global__ __launch_bounds__(1024) void ksortB(int N, int E) {
    __shared__ int wsums[32];
    __shared__ int carry_s;
    int tid = threadIdx.x, lane = tid & 31, wid = tid >> 5;
    if (tid == 0) carry_s = 0;
    __syncthreads();
    for (int base = 0; base < N; base += 1024) {
        int i = base + tid;
        int v = (i < N) ? g_cnt[i] : 0;
        int x = v;
        #pragma unroll
        for (int off = 1; off < 32; off <<= 1) {
            int t = __shfl_up_sync(0xffffffffu, x, off);
            if (lane >= off) x += t;
        }
        if (lane == 31) wsums[wid] = x;
        __syncthreads();
        if (wid == 0) {
            int y = wsums[lane];
            #pragma unroll
            for (int off = 1; off < 32; off <<= 1) {
                int t = __shfl_up_sync(0xffffffffu, y, off);
                if (lane >= off) y += t;
            }
            wsums[lane] = y;
        }
        __syncthreads();
        int excl = x - v + (wid > 0 ? wsums[wid - 1] : 0) + carry_s;
        if (i < N) { g_start[i] = excl; }
        __syncthreads();
        if (tid == 0) carry_s += wsums[31];
        __syncthreads();
    }
    if (tid == 0) g_start[N] = E;
}

__global__ void ksortB2(int N) {   // cursor copy (after scan)
    int i = blockIdx.x * blockDim.x + threadIdx.x;
    if (i < N) g_cnt[i] = g_start[i];
}

__global__ void ksortC(const void* __restrict__ edges, int E) {
    int e = blockIdx.x * blockDim.x + threadIdx.x;
    if (e >= E) return;
    int src, dst;
    load_edge(edges, e, g_is64, src, dst);
    int pos = atomicAdd(&g_cnt[src], 1);
    g_perm[pos] = make_int2(src, dst);
}

// ---------------------------------------------------------------------------
// K1: X = input @ W^T per head, packed f32x2 FMAs (unchanged).
__global__ __launch_bounds__(256) void k1_gemm(const float* __restrict__ A,
                                               const float* __restrict__ Wt,
                                               const float* __restrict__ av,
                                               int N) {
    const int h  = blockIdx.y;
    const int nb = blockIdx.x * 128;
    const int tid = threadIdx.x;
    const int tx = tid & 31;
    const int ty = tid >> 5;

    __shared__ float As[128][33];
    __shared__ float Bs2[32][130];
    __shared__ float redS[8][128];
    __shared__ float redD[8][128];

    unsigned long long acc[4][8];
    #pragma unroll
    for (int mi = 0; mi < 4; mi++)
        #pragma unroll
        for (int j = 0; j < 8; j++) acc[mi][j] = 0ull;

    for (int kk = 0; kk < 128; kk += 32) {
        #pragma unroll
        for (int r = 0; r < 4; r++) {
            int linear = r * 256 + tid;
            int row = linear >> 3;
            int kq  = (linear & 7) << 2;
            int n = nb + row;
            float4 va = make_float4(0.f, 0.f, 0.f, 0.f);
            if (n < N) va = *(const float4*)(A + n * 128 + kk + kq);
            As[row][kq] = va.x; As[row][kq + 1] = va.y;
            As[row][kq + 2] = va.z; As[row][kq + 3] = va.w;
            float4 vb = *(const float4*)(Wt + (h * 128 + row) * 128 + kk + kq);
            Bs2[kq][row]     = vb.x;
            Bs2[kq + 1][row] = vb.y;
            Bs2[kq + 2][row] = vb.z;
            Bs2[kq + 3][row] = vb.w;
        }
        __syncthreads();

        #pragma unroll
        for (int k = 0; k < 32; k++) {
            float a0 = As[tx][k];
            float a1 = As[tx + 32][k];
            float a2 = As[tx + 64][k];
            float a3 = As[tx + 96][k];
            unsigned long long a0d, a1d, a2d, a3d;
            asm("mov.b64 %0, {%1, %1};" : "=l"(a0d) : "f"(a0));
            asm("mov.b64 %0, {%1, %1};" : "=l"(a1d) : "f"(a1));
            asm("mov.b64 %0, {%1, %1};" : "=l"(a2d) : "f"(a2));
            asm("mov.b64 %0, {%1, %1};" : "=l"(a3d) : "f"(a3));
            #pragma unroll
            for (int j = 0; j < 8; j++) {
                unsigned long long b =
                    *(const unsigned long long*)&Bs2[k][ty * 16 + 2 * j];
                asm("fma.rn.f32x2 %0, %1, %2, %0;" : "+l"(acc[0][j]) : "l"(a0d), "l"(b));
                asm("fma.rn.f32x2 %0, %1, %2, %0;" : "+l"(acc[1][j]) : "l"(a1d), "l"(b));
                asm("fma.rn.f32x2 %0, %1, %2, %0;" : "+l"(acc[2][j]) : "l"(a2d), "l"(b));
                asm("fma.rn.f32x2 %0, %1, %2, %0;" : "+l"(acc[3][j]) : "l"(a3d), "l"(b));
            }
        }
        __syncthreads();
    }

    float accf[4][16];
    #pragma unroll
    for (int mi = 0; mi < 4; mi++)
        #pragma unroll
        for (int j = 0; j < 8; j++) {
            float lo, hi;
            asm("mov.b64 {%0, %1}, %2;" : "=f"(lo), "=f"(hi) : "l"(acc[mi][j]));
            accf[mi][2 * j] = lo; accf[mi][2 * j + 1] = hi;
        }

    float asv[16], adv[16];
    #pragma unroll
    for (int nj = 0; nj < 16; nj++) {
        int j = ty * 16 + nj;
        asv[nj] = av[h * 256 + j];
        adv[nj] = av[h * 256 + 128 + j];
    }

    float ps[4], pd[4];
    #pragma unroll
    for (int mi = 0; mi < 4; mi++) {
        int n = nb + tx + 32 * mi;
        float s = 0.f, d = 0.f;
        if (n < N) {
            size_t off = (size_t)n * 512 + h * 128 + ty * 16;
            float*  dst  = g_X + off;
            __half* hdst = g_Xh + off;
            #pragma unroll
            for (int nj = 0; nj < 16; nj++) {
                float v = accf[mi][nj];
                s = fmaf(v, asv[nj], s);
                d = fmaf(v, adv[nj], d);
            }
            #pragma unroll
            for (int q = 0; q < 4; q++) {
                float4 w4 = make_float4(accf[mi][q * 4], accf[mi][q * 4 + 1],
                                        accf[mi][q * 4 + 2], accf[mi][q * 4 + 3]);
                *(float4*)(dst + q * 4) = w4;
            }
            __half2 hh[8];
            #pragma unroll
            for (int j = 0; j < 8; j++)
                hh[j] = __floats2half2_rn(accf[mi][2 * j], accf[mi][2 * j + 1]);
            *(uint4*)hdst        = *(uint4*)&hh[0];
            *(uint4*)(hdst + 8)  = *(uint4*)&hh[4];
        }
        ps[mi] = s; pd[mi] = d;
    }

    #pragma unroll
    for (int mi = 0; mi < 4; mi++) {
        redS[ty][tx + 32 * mi] = ps[mi];
        redD[ty][tx + 32 * mi] = pd[mi];
    }
    __syncthreads();
    if (tid < 128) {
        int n = nb + tid;
        if (n < N) {
            float s = 0.f, d = 0.f;
            #pragma unroll
            for (int w = 0; w < 8; w++) { s += redS[w][tid]; d += redD[w][tid]; }
            g_sprm[n * 8 + h]     = s;
            g_sprm[n * 8 + 4 + h] = d;
        }
    }
}

// ---------------------------------------------------------------------------
// K3: iterate sorted slots; coalesced perm read + prob write; block sums.
__global__ __launch_bounds__(256) void k3_scores(int E) {
    __shared__ float wsum[8][4];
    int i = blockIdx.x * blockDim.x + threadIdx.x;
    int lane = threadIdx.x & 31, wid = threadIdx.x >> 5;

    float lp[4] = {0.f, 0.f, 0.f, 0.f};
    if (i < E) {
        int2 sd = g_perm[i];
        float4 sv = *(const float4*)(g_sprm + sd.x * 8);
        float4 dv = *(const float4*)(g_sprm + sd.y * 8 + 4);
        float s0 = sv.x + dv.x, s1 = sv.y + dv.y;
        float s2 = sv.z + dv.z, s3 = sv.w + dv.w;
        s0 = s0 > 0.f ? s0 : 0.01f * s0;
        s1 = s1 > 0.f ? s1 : 0.01f * s1;
        s2 = s2 > 0.f ? s2 : 0.01f * s2;
        s3 = s3 > 0.f ? s3 : 0.01f * s3;
        float4 p4 = make_float4(__expf(s0), __expf(s1), __expf(s2), __expf(s3));
        *(float4*)(g_sc + i * 4) = p4;
        lp[0] = p4.x; lp[1] = p4.y; lp[2] = p4.z; lp[3] = p4.w;
    }
    #pragma unroll
    for (int h = 0; h < 4; h++)
        #pragma unroll
        for (int off = 16; off > 0; off >>= 1)
            lp[h] += __shfl_xor_sync(0xffffffffu, lp[h], off);
    if (lane < 4) wsum[wid][lane] = lp[lane];
    __syncthreads();
    if (threadIdx.x < 4) {
        float s = 0.f;
        #pragma unroll
        for (int w = 0; w < 8; w++) s += wsum[w][threadIdx.x];
        atomicAdd(&g_hsum[threadIdx.x], s);
    }
}

// ---------------------------------------------------------------------------
// K5: warp-per-node: walk own bucket, accumulate, fuse head-mean, single store.
__global__ __launch_bounds__(256) void k5_agg(float* __restrict__ out, int N) {
    __shared__ float invZ[4];
    if (threadIdx.x < 4) invZ[threadIdx.x] = 0.25f / g_hsum[threadIdx.x];
    __syncthreads();

    int lane = threadIdx.x & 31;
    int n = blockIdx.x * 8 + (threadIdx.x >> 5);
    if (n >= N) return;

    int s = g_start[n], eend = g_start[n + 1];
    float4 acc = make_float4(0.f, 0.f, 0.f, 0.f);

    for (int i = s; i < eend; i++) {
        int dst = g_perm[i].y;
        float4 wv = *(const float4*)(g_sc + i * 4);
        float w[4] = {wv.x * invZ[0], wv.y * invZ[1],
                      wv.z * invZ[2], wv.w * invZ[3]};
        const __half2* xh = (const __half2*)g_Xh + (size_t)dst * 256;
        #pragma unroll
        for (int h = 0; h < 4; h++) {
            uint2 raw = *(const uint2*)(xh + h * 64 + lane * 2);
            float2 f0 = __half22float2(*(__half2*)&raw.x);
            float2 f1 = __half22float2(*(__half2*)&raw.y);
            acc.x = fmaf(w[h], f0.x, acc.x);
            acc.y = fmaf(w[h], f0.y, acc.y);
            acc.z = fmaf(w[h], f1.x, acc.z);
            acc.w = fmaf(w[h], f1.y, acc.w);
        }
    }

    // fused head-mean (fp32)
    const float4* xv = (const float4*)g_X + (size_t)n * 128;
    float4 m0 = xv[lane], m1 = xv[32 + lane], m2 = xv[64 + lane], m3 = xv[96 + lane];
    float4 r;
    r.x = fmaf(0.25f, m0.x + m1.x + m2.x + m3.x, acc.x);
    r.y = fmaf(0.25f, m0.y + m1.y + m2.y + m3.y, acc.y);
    r.z = fmaf(0.25f, m0.z + m1.z + m2.z + m3.z, acc.z);
    r.w = fmaf(0.25f, m0.w + m1.w + m2.w + m3.w, acc.w);
    ((float4*)out)[(size_t)n * 32 + lane] = r;
}

// ---------------------------------------------------------------------------
extern "C" void kernel_launch(void* const* d_in, const int* in_sizes, int n_in,
                              void* d_out, int out_size) {
    const float* input_h = (const float*)d_in[0];
    const void*  edges   = d_in[1];
    const float* W       = (const float*)d_in[2];
    const float* a       = (const float*)d_in[3];
    float* out = (float*)d_out;

    int N = in_sizes[0] / 128;   // 20000
    int E = in_sizes[1] / 3;     // 320000

    k0_detect<<<1, 32>>>((const unsigned int*)edges);
    kzero<<<(N + 255) / 256, 256>>>(N);
    ksortA<<<(E + 255) / 256, 256>>>(edges, E);
    ksortB<<<1, 1024>>>(N, E);
    ksortB2<<<(N + 255) / 256, 256>>>(N);
    ksortC<<<(E + 255) / 256, 256>>>(edges, E);

    dim3 g1((N + 127) / 128, 4);
    k1_gemm<<<g1, 256>>>(input_h, W, a, N);

    k3_scores<<<(E + 255) / 256, 256>>>(E);

    k5_agg<<<(N + 7) / 8, 256>>>(out, N);
}

// round 6
// speedup vs baseline: 1.0910x; 1.0910x over previous
#include <cuda_runtime.h>
#include <cuda_fp16.h>

#define NMAX 20000
#define EMAX 320000

__device__ float  g_X[NMAX * 512];       // fp32 X[n][h*128+o]
__device__ __half g_Xh[NMAX * 512];      // fp16 copy for gathers
__device__ float  g_sprm[NMAX * 8];      // [n*8+h]=s_src, [n*8+4+h]=s_dst
__device__ float  g_sc[EMAX * 4];        // exp(score), slot-major float4
__device__ int2   g_perm[EMAX];          // sorted-by-src {src, dst}
__device__ int    g_cnt[NMAX];           // histogram -> cursor
__device__ int    g_start[NMAX + 1];     // bucket starts
__device__ int    g_bsum[128];           // per-block sums for scan
__device__ float  g_hsum[4];
__device__ int    g_is64;

// ---------------------------------------------------------------------------
__global__ void k0_detect(const unsigned int* e32) {
    if (blockIdx.x == 0 && threadIdx.x == 0) {
        int is64 = 1;
        #pragma unroll 1
        for (int i = 0; i < 32; i++) {
            if (e32[2 * i + 1] != 0u) { is64 = 0; break; }
        }
        g_is64 = is64;
    }
}

__device__ __forceinline__ void load_edge(const void* edges, int e, int is64,
                                          int& src, int& dst) {
    if (is64) {
        const long long* p = (const long long*)edges;
        src = (int)p[3 * e];
        dst = (int)p[3 * e + 2];
    } else {
        const int* p = (const int*)edges;
        src = p[3 * e];
        dst = p[3 * e + 2];
    }
}

// ---------------------------------------------------------------------------
__global__ void kzero(int N) {
    int i = blockIdx.x * blockDim.x + threadIdx.x;
    if (i < N) g_cnt[i] = 0;
    if (i < 4) g_hsum[i] = 0.f;
}

__global__ void ksortA(const void* __restrict__ edges, int E) {
    int e = blockIdx.x * blockDim.x + threadIdx.x;
    if (e >= E) return;
    int src, dst;
    load_edge(edges, e, g_is64, src, dst);
    atomicAdd(&g_cnt[src], 1);
}

// Phase 1: per-block (256 counters) sums
__global__ __launch_bounds__(256) void kscan1(int N) {
    __shared__ int ws[8];
    int i = blockIdx.x * 256 + threadIdx.x;
    int lane = threadIdx.x & 31, wid = threadIdx.x >> 5;
    int v = (i < N) ? g_cnt[i] : 0;
    int x = v;
    #pragma unroll
    for (int off = 16; off > 0; off >>= 1)
        x += __shfl_xor_sync(0xffffffffu, x, off);
    if (lane == 0) ws[wid] = x;
    __syncthreads();
    if (threadIdx.x == 0) {
        int s = 0;
        #pragma unroll
        for (int w = 0; w < 8; w++) s += ws[w];
        g_bsum[blockIdx.x] = s;
    }
}

// Phase 2: exclusive scan of <=128 block sums (one tiny block)
__global__ __launch_bounds__(128) void kscan2(int nb, int N, int E) {
    __shared__ int sh[128];
    int t = threadIdx.x;
    int v = (t < nb) ? g_bsum[t] : 0;
    sh[t] = v;
    __syncthreads();
    #pragma unroll
    for (int off = 1; off < 128; off <<= 1) {
        int tv = (t >= off) ? sh[t - off] : 0;
        __syncthreads();
        sh[t] += tv;
        __syncthreads();
    }
    if (t < nb) g_bsum[t] = sh[t] - v;   // exclusive
    if (t == 0) g_start[N] = E;
}

// Phase 3: per-block local exclusive scan + global offset; write start + cursor
__global__ __launch_bounds__(256) void kscan3(int N) {
    __shared__ int ws[8];
    int i = blockIdx.x * 256 + threadIdx.x;
    int lane = threadIdx.x & 31, wid = threadIdx.x >> 5;
    int v = (i < N) ? g_cnt[i] : 0;
    int x = v;
    #pragma unroll
    for (int off = 1; off < 32; off <<= 1) {
        int t = __shfl_up_sync(0xffffffffu, x, off);
        if (lane >= off) x += t;
    }
    if (lane == 31) ws[wid] = x;
    __syncthreads();
    if (wid == 0 && lane < 8) {
        int y = ws[lane];
        #pragma unroll
        for (int off = 1; off < 8; off <<= 1) {
            int t = __shfl_up_sync(0xffu, y, off);
            if (lane >= off) y += t;
        }
        ws[lane] = y;
    }
    __syncthreads();
    int excl = x - v + (wid > 0 ? ws[wid - 1] : 0) + g_bsum[blockIdx.x];
    if (i < N) {
        g_start[i] = excl;
        g_cnt[i]   = excl;   // scatter cursor
    }
}

__global__ void ksortC(const void* __restrict__ edges, int E) {
    int e = blockIdx.x * blockDim.x + threadIdx.x;
    if (e >= E) return;
    int src, dst;
    load_edge(edges, e, g_is64, src, dst);
    int pos = atomicAdd(&g_cnt[src], 1);
    g_perm[pos] = make_int2(src, dst);
}

// ---------------------------------------------------------------------------
// K1: X = input @ W^T per head, packed f32x2 FMAs.
__global__ __launch_bounds__(256) void k1_gemm(const float* __restrict__ A,
                                               const float* __restrict__ Wt,
                                               const float* __restrict__ av,
                                               int N) {
    const int h  = blockIdx.y;
    const int nb = blockIdx.x * 128;
    const int tid = threadIdx.x;
    const int tx = tid & 31;
    const int ty = tid >> 5;

    __shared__ float As[128][33];
    __shared__ float Bs2[32][130];
    __shared__ float redS[8][128];
    __shared__ float redD[8][128];

    unsigned long long acc[4][8];
    #pragma unroll
    for (int mi = 0; mi < 4; mi++)
        #pragma unroll
        for (int j = 0; j < 8; j++) acc[mi][j] = 0ull;

    for (int kk = 0; kk < 128; kk += 32) {
        #pragma unroll
        for (int r = 0; r < 4; r++) {
            int linear = r * 256 + tid;
            int row = linear >> 3;
            int kq  = (linear & 7) << 2;
            int n = nb + row;
            float4 va = make_float4(0.f, 0.f, 0.f, 0.f);
            if (n < N) va = *(const float4*)(A + n * 128 + kk + kq);
            As[row][kq] = va.x; As[row][kq + 1] = va.y;
            As[row][kq + 2] = va.z; As[row][kq + 3] = va.w;
            float4 vb = *(const float4*)(Wt + (h * 128 + row) * 128 + kk + kq);
            Bs2[kq][row]     = vb.x;
            Bs2[kq + 1][row] = vb.y;
            Bs2[kq + 2][row] = vb.z;
            Bs2[kq + 3][row] = vb.w;
        }
        __syncthreads();

        #pragma unroll
        for (int k = 0; k < 32; k++) {
            float a0 = As[tx][k];
            float a1 = As[tx + 32][k];
            float a2 = As[tx + 64][k];
            float a3 = As[tx + 96][k];
            unsigned long long a0d, a1d, a2d, a3d;
            asm("mov.b64 %0, {%1, %1};" : "=l"(a0d) : "f"(a0));
            asm("mov.b64 %0, {%1, %1};" : "=l"(a1d) : "f"(a1));
            asm("mov.b64 %0, {%1, %1};" : "=l"(a2d) : "f"(a2));
            asm("mov.b64 %0, {%1, %1};" : "=l"(a3d) : "f"(a3));
            #pragma unroll
            for (int j = 0; j < 8; j++) {
                unsigned long long b =
                    *(const unsigned long long*)&Bs2[k][ty * 16 + 2 * j];
                asm("fma.rn.f32x2 %0, %1, %2, %0;" : "+l"(acc[0][j]) : "l"(a0d), "l"(b));
                asm("fma.rn.f32x2 %0, %1, %2, %0;" : "+l"(acc[1][j]) : "l"(a1d), "l"(b));
                asm("fma.rn.f32x2 %0, %1, %2, %0;" : "+l"(acc[2][j]) : "l"(a2d), "l"(b));
                asm("fma.rn.f32x2 %0, %1, %2, %0;" : "+l"(acc[3][j]) : "l"(a3d), "l"(b));
            }
        }
        __syncthreads();
    }

    float accf[4][16];
    #pragma unroll
    for (int mi = 0; mi < 4; mi++)
        #pragma unroll
        for (int j = 0; j < 8; j++) {
            float lo, hi;
            asm("mov.b64 {%0, %1}, %2;" : "=f"(lo), "=f"(hi) : "l"(acc[mi][j]));
            accf[mi][2 * j] = lo; accf[mi][2 * j + 1] = hi;
        }

    float asv[16], adv[16];
    #pragma unroll
    for (int nj = 0; nj < 16; nj++) {
        int j = ty * 16 + nj;
        asv[nj] = av[h * 256 + j];
        adv[nj] = av[h * 256 + 128 + j];
    }

    float ps[4], pd[4];
    #pragma unroll
    for (int mi = 0; mi < 4; mi++) {
        int n = nb + tx + 32 * mi;
        float s = 0.f, d = 0.f;
        if (n < N) {
            size_t off = (size_t)n * 512 + h * 128 + ty * 16;
            float*  dst  = g_X + off;
            __half* hdst = g_Xh + off;
            #pragma unroll
            for (int nj = 0; nj < 16; nj++) {
                float v = accf[mi][nj];
                s = fmaf(v, asv[nj], s);
                d = fmaf(v, adv[nj], d);
            }
            #pragma unroll
            for (int q = 0; q < 4; q++) {
                float4 w4 = make_float4(accf[mi][q * 4], accf[mi][q * 4 + 1],
                                        accf[mi][q * 4 + 2], accf[mi][q * 4 + 3]);
                *(float4*)(dst + q * 4) = w4;
            }
            __half2 hh[8];
            #pragma unroll
            for (int j = 0; j < 8; j++)
                hh[j] = __floats2half2_rn(accf[mi][2 * j], accf[mi][2 * j + 1]);
            *(uint4*)hdst        = *(uint4*)&hh[0];
            *(uint4*)(hdst + 8)  = *(uint4*)&hh[4];
        }
        ps[mi] = s; pd[mi] = d;
    }

    #pragma unroll
    for (int mi = 0; mi < 4; mi++) {
        redS[ty][tx + 32 * mi] = ps[mi];
        redD[ty][tx + 32 * mi] = pd[mi];
    }
    __syncthreads();
    if (tid < 128) {
        int n = nb + tid;
        if (n < N) {
            float s = 0.f, d = 0.f;
            #pragma unroll
            for (int w = 0; w < 8; w++) { s += redS[w][tid]; d += redD[w][tid]; }
            g_sprm[n * 8 + h]     = s;
            g_sprm[n * 8 + 4 + h] = d;
        }
    }
}

// ---------------------------------------------------------------------------
// K3: iterate sorted slots; coalesced perm read + prob write; block sums.
__global__ __launch_bounds__(256) void k3_scores(int E) {
    __shared__ float wsum[8][4];
    int i = blockIdx.x * blockDim.x + threadIdx.x;
    int lane = threadIdx.x & 31, wid = threadIdx.x >> 5;

    float lp[4] = {0.f, 0.f, 0.f, 0.f};
    if (i < E) {
        int2 sd = g_perm[i];
        float4 sv = *(const float4*)(g_sprm + sd.x * 8);
        float4 dv = *(const float4*)(g_sprm + sd.y * 8 + 4);
        float s0 = sv.x + dv.x, s1 = sv.y + dv.y;
        float s2 = sv.z + dv.z, s3 = sv.w + dv.w;
        s0 = s0 > 0.f ? s0 : 0.01f * s0;
        s1 = s1 > 0.f ? s1 : 0.01f * s1;
        s2 = s2 > 0.f ? s2 : 0.01f * s2;
        s3 = s3 > 0.f ? s3 : 0.01f * s3;
        float4 p4 = make_float4(__expf(s0), __expf(s1), __expf(s2), __expf(s3));
        *(float4*)(g_sc + i * 4) = p4;
        lp[0] = p4.x; lp[1] = p4.y; lp[2] = p4.z; lp[3] = p4.w;
    }
    #pragma unroll
    for (int h = 0; h < 4; h++)
        #pragma unroll
        for (int off = 16; off > 0; off >>= 1)
            lp[h] += __shfl_xor_sync(0xffffffffu, lp[h], off);
    if (lane < 4) wsum[wid][lane] = lp[lane];
    __syncthreads();
    if (threadIdx.x < 4) {
        float s = 0.f;
        #pragma unroll
        for (int w = 0; w < 8; w++) s += wsum[w][threadIdx.x];
        atomicAdd(&g_hsum[threadIdx.x], s);
    }
}

// ---------------------------------------------------------------------------
// K5: warp-per-node: walk bucket, accumulate, fuse head-mean, single store.
__global__ __launch_bounds__(256) void k5_agg(float* __restrict__ out, int N) {
    __shared__ float invZ[4];
    if (threadIdx.x < 4) invZ[threadIdx.x] = 0.25f / g_hsum[threadIdx.x];
    __syncthreads();

    int lane = threadIdx.x & 31;
    int n = blockIdx.x * 8 + (threadIdx.x >> 5);
    if (n >= N) return;

    int s = g_start[n], eend = g_start[n + 1];
    float4 acc = make_float4(0.f, 0.f, 0.f, 0.f);

    for (int i = s; i < eend; i++) {
        int dst = g_perm[i].y;
        float4 wv = *(const float4*)(g_sc + i * 4);
        float w[4] = {wv.x * invZ[0], wv.y * invZ[1],
                      wv.z * invZ[2], wv.w * invZ[3]};
        const __half2* xh = (const __half2*)g_Xh + (size_t)dst * 256;
        #pragma unroll
        for (int h = 0; h < 4; h++) {
            uint2 raw = *(const uint2*)(xh + h * 64 + lane * 2);
            float2 f0 = __half22float2(*(__half2*)&raw.x);
            float2 f1 = __half22float2(*(__half2*)&raw.y);
            acc.x = fmaf(w[h], f0.x, acc.x);
            acc.y = fmaf(w[h], f0.y, acc.y);
            acc.z = fmaf(w[h], f1.x, acc.z);
            acc.w = fmaf(w[h], f1.y, acc.w);
        }
    }

    const float4* xv = (const float4*)g_X + (size_t)n * 128;
    float4 m0 = xv[lane], m1 = xv[32 + lane], m2 = xv[64 + lane], m3 = xv[96 + lane];
    float4 r;
    r.x = fmaf(0.25f, m0.x + m1.x + m2.x + m3.x, acc.x);
    r.y = fmaf(0.25f, m0.y + m1.y + m2.y + m3.y, acc.y);
    r.z = fmaf(0.25f, m0.z + m1.z + m2.z + m3.z, acc.z);
    r.w = fmaf(0.25f, m0.w + m1.w + m2.w + m3.w, acc.w);
    ((float4*)out)[(size_t)n * 32 + lane] = r;
}

// ---------------------------------------------------------------------------
extern "C" void kernel_launch(void* const* d_in, const int* in_sizes, int n_in,
                              void* d_out, int out_size) {
    const float* input_h = (const float*)d_in[0];
    const void*  edges   = d_in[1];
    const float* W       = (const float*)d_in[2];
    const float* a       = (const float*)d_in[3];
    float* out = (float*)d_out;

    int N = in_sizes[0] / 128;   // 20000
    int E = in_sizes[1] / 3;     // 320000
    int nb = (N + 255) / 256;    // scan blocks (<=128)

    k0_detect<<<1, 32>>>((const unsigned int*)edges);
    kzero<<<nb, 256>>>(N);
    ksortA<<<(E + 255) / 256, 256>>>(edges, E);
    kscan1<<<nb, 256>>>(N);
    kscan2<<<1, 128>>>(nb, N, E);
    kscan3<<<nb, 256>>>(N);
    ksortC<<<(E + 255) / 256, 256>>>(edges, E);

    dim3 g1((N + 127) / 128, 4);
    k1_gemm<<<g1, 256>>>(input_h, W, a, N);

    k3_scores<<<(E + 255) / 256, 256>>>(E);

    k5_agg<<<(N + 7) / 8, 256>>>(out, N);
}

// round 8
// speedup vs baseline: 1.3531x; 1.2402x over previous
#include <cuda_runtime.h>
#include <cuda_fp16.h>
#include <cuda_bf16.h>
#include <cstdint>

#define NMAX 20000
#define EMAX 320000

__device__ float  g_X[NMAX * 512];       // fp32 X[n][h*128+o]
__device__ __half g_Xh[NMAX * 512];      // fp16 copy for gathers
__device__ float  g_sprm[NMAX * 8];      // [n*8+h]=s_src, [n*8+4+h]=s_dst
__device__ float  g_sc[EMAX * 4];        // exp(score), slot-major float4
__device__ int2   g_perm[EMAX];          // sorted-by-src {src, dst}
__device__ int    g_cnt[NMAX];           // histogram -> cursor
__device__ int    g_start[NMAX + 1];     // bucket starts
__device__ int    g_bsum[128];           // per-block sums for scan
__device__ float  g_hsum[4];
__device__ int    g_is64;

// ---------------------------------------------------------------------------
__device__ __forceinline__ uint32_t smem_u32(const void* p) {
    uint32_t a;
    asm("{ .reg .u64 t; cvta.to.shared.u64 t, %1; cvt.u32.u64 %0, t; }"
        : "=r"(a) : "l"(p));
    return a;
}

#define LDSM4(r, a)                                                            \
    asm volatile("ldmatrix.sync.aligned.m8n8.x4.shared.b16 {%0,%1,%2,%3}, [%4];" \
        : "=r"((r)[0]), "=r"((r)[1]), "=r"((r)[2]), "=r"((r)[3]) : "r"(a))

#define MMA16816(d, a, b0, b1)                                                 \
    asm volatile("mma.sync.aligned.m16n8k16.row.col.f32.bf16.bf16.f32 "        \
        "{%0,%1,%2,%3}, {%4,%5,%6,%7}, {%8,%9}, {%0,%1,%2,%3};"                \
        : "+f"((d)[0]), "+f"((d)[1]), "+f"((d)[2]), "+f"((d)[3])               \
        : "r"((a)[0]), "r"((a)[1]), "r"((a)[2]), "r"((a)[3]), "r"(b0), "r"(b1))

// smem layout (bytes): av | Ahi | Alo | Bhi | Blo  (stage reuses Ahi+Alo)
#define TS       136                    // bf16 row stride (272 B, LDSM-friendly)
#define SM_AV    0                      // 256 floats = 1024 B
#define SM_AHI   1024
#define SM_ALO   (1024 + 34816)         // 35840
#define SM_BHI   (35840 + 34816)        // 70656
#define SM_BLO   (70656 + 34816)        // 105472
#define K1_SMEM  140288
#define SM_STAGE 1024                   // reuse A region: 128*132*4 = 67584
#define SSTR     132                    // stage float stride

// ---------------------------------------------------------------------------
__global__ void k0_detect(const unsigned int* e32) {
    if (blockIdx.x == 0 && threadIdx.x == 0) {
        int is64 = 1;
        #pragma unroll 1
        for (int i = 0; i < 32; i++) {
            if (e32[2 * i + 1] != 0u) { is64 = 0; break; }
        }
        g_is64 = is64;
    }
}

__device__ __forceinline__ void load_edge(const void* edges, int e, int is64,
                                          int& src, int& dst) {
    if (is64) {
        const long long* p = (const long long*)edges;
        src = (int)p[3 * e];
        dst = (int)p[3 * e + 2];
    } else {
        const int* p = (const int*)edges;
        src = p[3 * e];
        dst = p[3 * e + 2];
    }
}

// ---------------------------------------------------------------------------
__global__ void kzero(int N) {
    int i = blockIdx.x * blockDim.x + threadIdx.x;
    if (i < N) g_cnt[i] = 0;
    if (i < 4) g_hsum[i] = 0.f;
}

__global__ void ksortA(const void* __restrict__ edges, int E) {
    int e = blockIdx.x * blockDim.x + threadIdx.x;
    if (e >= E) return;
    int src, dst;
    load_edge(edges, e, g_is64, src, dst);
    atomicAdd(&g_cnt[src], 1);
}

__global__ __launch_bounds__(256) void kscan1(int N) {
    __shared__ int ws[8];
    int i = blockIdx.x * 256 + threadIdx.x;
    int lane = threadIdx.x & 31, wid = threadIdx.x >> 5;
    int v = (i < N) ? g_cnt[i] : 0;
    int x = v;
    #pragma unroll
    for (int off = 16; off > 0; off >>= 1)
        x += __shfl_xor_sync(0xffffffffu, x, off);
    if (lane == 0) ws[wid] = x;
    __syncthreads();
    if (threadIdx.x == 0) {
        int s = 0;
        #pragma unroll
        for (int w = 0; w < 8; w++) s += ws[w];
        g_bsum[blockIdx.x] = s;
    }
}

__global__ __launch_bounds__(128) void kscan2(int nb, int N, int E) {
    __shared__ int sh[128];
    int t = threadIdx.x;
    int v = (t < nb) ? g_bsum[t] : 0;
    sh[t] = v;
    __syncthreads();
    #pragma unroll
    for (int off = 1; off < 128; off <<= 1) {
        int tv = (t >= off) ? sh[t - off] : 0;
        __syncthreads();
        sh[t] += tv;
        __syncthreads();
    }
    if (t < nb) g_bsum[t] = sh[t] - v;
    if (t == 0) g_start[N] = E;
}

__global__ __launch_bounds__(256) void kscan3(int N) {
    __shared__ int ws[8];
    int i = blockIdx.x * 256 + threadIdx.x;
    int lane = threadIdx.x & 31, wid = threadIdx.x >> 5;
    int v = (i < N) ? g_cnt[i] : 0;
    int x = v;
    #pragma unroll
    for (int off = 1; off < 32; off <<= 1) {
        int t = __shfl_up_sync(0xffffffffu, x, off);
        if (lane >= off) x += t;
    }
    if (lane == 31) ws[wid] = x;
    __syncthreads();
    if (wid == 0 && lane < 8) {
        int y = ws[lane];
        #pragma unroll
        for (int off = 1; off < 8; off <<= 1) {
            int t = __shfl_up_sync(0xffu, y, off);
            if (lane >= off) y += t;
        }
        ws[lane] = y;
    }
    __syncthreads();
    int excl = x - v + (wid > 0 ? ws[wid - 1] : 0) + g_bsum[blockIdx.x];
    if (i < N) {
        g_start[i] = excl;
        g_cnt[i]   = excl;
    }
}

__global__ void ksortC(const void* __restrict__ edges, int E) {
    int e = blockIdx.x * blockDim.x + threadIdx.x;
    if (e >= E) return;
    int src, dst;
    load_edge(edges, e, g_is64, src, dst);
    int pos = atomicAdd(&g_cnt[src], 1);
    g_perm[pos] = make_int2(src, dst);
}

// ---------------------------------------------------------------------------
// bf16 hi/lo split + pack (pair c,c+1 -> one u32, low half = c)
__device__ __forceinline__ void split_pack(float x, float y,
                                           uint32_t& hi, uint32_t& lo) {
    __nv_bfloat16 hx = __float2bfloat16(x), hy = __float2bfloat16(y);
    __nv_bfloat16 lx = __float2bfloat16(x - __bfloat162float(hx));
    __nv_bfloat16 ly = __float2bfloat16(y - __bfloat162float(hy));
    hi = ((uint32_t)*(unsigned short*)&hy << 16) | *(unsigned short*)&hx;
    lo = ((uint32_t)*(unsigned short*)&ly << 16) | *(unsigned short*)&lx;
}

// K1: HMMA bf16-split GEMM. CTA: 128 nodes x 128 cols (head = blockIdx.y), K=128.
__global__ __launch_bounds__(256) void k1_mma(const float* __restrict__ A,
                                              const float* __restrict__ Wt,
                                              const float* __restrict__ av,
                                              int N) {
    extern __shared__ char smem[];
    const uint32_t sbase = smem_u32(smem);
    const int h   = blockIdx.y;
    const int nb  = blockIdx.x * 128;
    const int tid = threadIdx.x;
    const int lane = tid & 31, wid = tid >> 5;

    float* sAv = (float*)(smem + SM_AV);
    if (tid < 256) sAv[tid] = av[h * 256 + tid];

    // ---- fill A hi/lo tiles (128 rows x 128 k)
    #pragma unroll
    for (int it = 0; it < 16; it++) {
        int g = it * 256 + tid;          // 4096 float4 granules
        int row = g >> 5;
        int kq  = (g & 31) << 2;
        int n = nb + row;
        float4 v = make_float4(0.f, 0.f, 0.f, 0.f);
        if (n < N) v = *(const float4*)(A + (size_t)n * 128 + kq);
        uint32_t h0, l0, h1, l1;
        split_pack(v.x, v.y, h0, l0);
        split_pack(v.z, v.w, h1, l1);
        uint32_t off = (row * TS + kq) * 2;
        *(uint2*)(smem + SM_AHI + off) = make_uint2(h0, h1);
        *(uint2*)(smem + SM_ALO + off) = make_uint2(l0, l1);
    }
    // ---- fill B hi/lo tiles (128 weight rows x 128 k)
    #pragma unroll
    for (int it = 0; it < 16; it++) {
        int g = it * 256 + tid;
        int row = g >> 5;
        int kq  = (g & 31) << 2;
        float4 v = *(const float4*)(Wt + (size_t)(h * 128 + row) * 128 + kq);
        uint32_t h0, l0, h1, l1;
        split_pack(v.x, v.y, h0, l0);
        split_pack(v.z, v.w, h1, l1);
        uint32_t off = (row * TS + kq) * 2;
        *(uint2*)(smem + SM_BHI + off) = make_uint2(h0, h1);
        *(uint2*)(smem + SM_BLO + off) = make_uint2(l0, l1);
    }
    __syncthreads();

    // warp tile: 64 (M) x 32 (N); warps 2 x 4
    const int m0 = (wid & 1) * 64;
    const int n0 = (wid >> 1) * 32;

    // ldmatrix per-thread byte offsets
    uint32_t offA[4], offB[2];
    {
        int rowA = m0 + (lane & 15);
        int colA = (lane >> 4) << 3;
        #pragma unroll
        for (int mi = 0; mi < 4; mi++)
            offA[mi] = ((rowA + mi * 16) * TS + colA) * 2;
        int nB = n0 + (lane & 7) + ((lane >> 4) << 3);
        int kB = ((lane >> 3) & 1) << 3;
        #pragma unroll
        for (int nbi = 0; nbi < 2; nbi++)
            offB[nbi] = ((nB + nbi * 16) * TS + kB) * 2;
    }

    float acc[4][4][4];
    #pragma unroll
    for (int mi = 0; mi < 4; mi++)
        #pragma unroll
        for (int ni = 0; ni < 4; ni++)
            #pragma unroll
            for (int q = 0; q < 4; q++) acc[mi][ni][q] = 0.f;

    const uint32_t aHi = sbase + SM_AHI, aLo = sbase + SM_ALO;
    const uint32_t bHi = sbase + SM_BHI, bLo = sbase + SM_BLO;

    #pragma unroll
    for (int ks = 0; ks < 8; ks++) {
        uint32_t AH[4][4], AL[4][4], BH[2][4], BL[2][4];
        #pragma unroll
        for (int mi = 0; mi < 4; mi++) {
            LDSM4(AH[mi], aHi + offA[mi] + ks * 32);
            LDSM4(AL[mi], aLo + offA[mi] + ks * 32);
        }
        #pragma unroll
        for (int nbi = 0; nbi < 2; nbi++) {
            LDSM4(BH[nbi], bHi + offB[nbi] + ks * 32);
            LDSM4(BL[nbi], bLo + offB[nbi] + ks * 32);
        }
        #pragma unroll
        for (int mi = 0; mi < 4; mi++)
            #pragma unroll
            for (int ni = 0; ni < 4; ni++) {
                int gsel = ni >> 1, p = (ni & 1) * 2;
                MMA16816(acc[mi][ni], AH[mi], BH[gsel][p], BH[gsel][p + 1]);
                MMA16816(acc[mi][ni], AH[mi], BL[gsel][p], BL[gsel][p + 1]);
                MMA16816(acc[mi][ni], AL[mi], BH[gsel][p], BH[gsel][p + 1]);
            }
    }

    __syncthreads();   // done reading A/B smem; reuse as stage

    float* stage = (float*)(smem + SM_STAGE);
    {
        int r = m0 + (lane >> 2);
        int c = n0 + 2 * (lane & 3);
        #pragma unroll
        for (int mi = 0; mi < 4; mi++)
            #pragma unroll
            for (int ni = 0; ni < 4; ni++) {
                int rr = r + mi * 16, cc = c + ni * 8;
                *(float2*)&stage[rr * SSTR + cc] =
                    make_float2(acc[mi][ni][0], acc[mi][ni][1]);
                *(float2*)&stage[(rr + 8) * SSTR + cc] =
                    make_float2(acc[mi][ni][2], acc[mi][ni][3]);
            }
    }
    __syncthreads();

    // per-thread full-row attention dots
    if (tid < 128) {
        int n = nb + tid;
        if (n < N) {
            float s = 0.f, d = 0.f;
            #pragma unroll
            for (int j = 0; j < 32; j++) {
                float4 xv = *(float4*)&stage[tid * SSTR + j * 4];
                float4 as = *(float4*)&sAv[j * 4];
                float4 ad = *(float4*)&sAv[128 + j * 4];
                s = fmaf(xv.x, as.x, fmaf(xv.y, as.y,
                    fmaf(xv.z, as.z, fmaf(xv.w, as.w, s))));
                d = fmaf(xv.x, ad.x, fmaf(xv.y, ad.y,
                    fmaf(xv.z, ad.z, fmaf(xv.w, ad.w, d))));
            }
            g_sprm[n * 8 + h]     = s;
            g_sprm[n * 8 + 4 + h] = d;
        }
    }

    // coalesced X / Xh writes: warp w handles rows w*16..w*16+15
    #pragma unroll
    for (int rr = 0; rr < 16; rr++) {
        int row = (tid >> 5) * 16 + rr;
        int n = nb + row;
        if (n < N) {
            float4 v = *(float4*)&stage[row * SSTR + lane * 4];
            size_t off = (size_t)n * 512 + h * 128 + lane * 4;
            *(float4*)(g_X + off) = v;
            __half2 p0 = __floats2half2_rn(v.x, v.y);
            __half2 p1 = __floats2half2_rn(v.z, v.w);
            *(uint2*)(g_Xh + off) =
                make_uint2(*(uint32_t*)&p0, *(uint32_t*)&p1);
        }
    }
}

// ---------------------------------------------------------------------------
// K3: iterate sorted slots; coalesced perm read + prob write; block sums.
__global__ __launch_bounds__(256) void k3_scores(int E) {
    __shared__ float wsum[8][4];
    int i = blockIdx.x * blockDim.x + threadIdx.x;
    int lane = threadIdx.x & 31, wid = threadIdx.x >> 5;

    float lp[4] = {0.f, 0.f, 0.f, 0.f};
    if (i < E) {
        int2 sd = g_perm[i];
        float4 sv = *(const float4*)(g_sprm + sd.x * 8);
        float4 dv = *(const float4*)(g_sprm + sd.y * 8 + 4);
        float s0 = sv.x + dv.x, s1 = sv.y + dv.y;
        float s2 = sv.z + dv.z, s3 = sv.w + dv.w;
        s0 = s0 > 0.f ? s0 : 0.01f * s0;
        s1 = s1 > 0.f ? s1 : 0.01f * s1;
        s2 = s2 > 0.f ? s2 : 0.01f * s2;
        s3 = s3 > 0.f ? s3 : 0.01f * s3;
        float4 p4 = make_float4(__expf(s0), __expf(s1), __expf(s2), __expf(s3));
        *(float4*)(g_sc + i * 4) = p4;
        lp[0] = p4.x; lp[1] = p4.y; lp[2] = p4.z; lp[3] = p4.w;
    }
    #pragma unroll
    for (int h = 0; h < 4; h++)
        #pragma unroll
        for (int off = 16; off > 0; off >>= 1)
            lp[h] += __shfl_xor_sync(0xffffffffu, lp[h], off);
    if (lane < 4) wsum[wid][lane] = lp[lane];
    __syncthreads();
    if (threadIdx.x < 4) {
        float s = 0.f;
        #pragma unroll
        for (int w = 0; w < 8; w++) s += wsum[w][threadIdx.x];
        atomicAdd(&g_hsum[threadIdx.x], s);
    }
}

// ---------------------------------------------------------------------------
// K5: warp-per-node: walk bucket, accumulate, fuse head-mean, single store.
__global__ __launch_bounds__(256) void k5_agg(float* __restrict__ out, int N) {
    __shared__ float invZ[4];
    if (threadIdx.x < 4) invZ[threadIdx.x] = 0.25f / g_hsum[threadIdx.x];
    __syncthreads();

    int lane = threadIdx.x & 31;
    int n = blockIdx.x * 8 + (threadIdx.x >> 5);
    if (n >= N) return;

    int s = g_start[n], eend = g_start[n + 1];
    float4 acc = make_float4(0.f, 0.f, 0.f, 0.f);

    for (int i = s; i < eend; i++) {
        int dst = g_perm[i].y;
        float4 wv = *(const float4*)(g_sc + i * 4);
        float w[4] = {wv.x * invZ[0], wv.y * invZ[1],
                      wv.z * invZ[2], wv.w * invZ[3]};
        const __half2* xh = (const __half2*)g_Xh + (size_t)dst * 256;
        #pragma unroll
        for (int h = 0; h < 4; h++) {
            uint2 raw = *(const uint2*)(xh + h * 64 + lane * 2);
            float2 f0 = __half22float2(*(__half2*)&raw.x);
            float2 f1 = __half22float2(*(__half2*)&raw.y);
            acc.x = fmaf(w[h], f0.x, acc.x);
            acc.y = fmaf(w[h], f0.y, acc.y);
            acc.z = fmaf(w[h], f1.x, acc.z);
            acc.w = fmaf(w[h], f1.y, acc.w);
        }
    }

    const float4* xv = (const float4*)g_X + (size_t)n * 128;
    float4 m0 = xv[lane], m1 = xv[32 + lane], m2 = xv[64 + lane], m3 = xv[96 + lane];
    float4 r;
    r.x = fmaf(0.25f, m0.x + m1.x + m2.x + m3.x, acc.x);
    r.y = fmaf(0.25f, m0.y + m1.y + m2.y + m3.y, acc.y);
    r.z = fmaf(0.25f, m0.z + m1.z + m2.z + m3.z, acc.z);
    r.w = fmaf(0.25f, m0.w + m1.w + m2.w + m3.w, acc.w);
    ((float4*)out)[(size_t)n * 32 + lane] = r;
}

// ---------------------------------------------------------------------------
extern "C" void kernel_launch(void* const* d_in, const int* in_sizes, int n_in,
                              void* d_out, int out_size) {
    const float* input_h = (const float*)d_in[0];
    const void*  edges   = d_in[1];
    const float* W       = (const float*)d_in[2];
    const float* a       = (const float*)d_in[3];
    float* out = (float*)d_out;

    int N = in_sizes[0] / 128;   // 20000
    int E = in_sizes[1] / 3;     // 320000
    int nb = (N + 255) / 256;

    cudaFuncSetAttribute(k1_mma, cudaFuncAttributeMaxDynamicSharedMemorySize,
                         K1_SMEM);

    k0_detect<<<1, 32>>>((const unsigned int*)edges);
    kzero<<<nb, 256>>>(N);
    ksortA<<<(E + 255) / 256, 256>>>(edges, E);
    kscan1<<<nb, 256>>>(N);
    kscan2<<<1, 128>>>(nb, N, E);
    kscan3<<<nb, 256>>>(N);
    ksortC<<<(E + 255) / 256, 256>>>(edges, E);

    dim3 g1((N + 127) / 128, 4);
    k1_mma<<<g1, 256, K1_SMEM>>>(input_h, W, a, N);

    k3_scores<<<(E + 255) / 256, 256>>>(E);

    k5_agg<<<(N + 7) / 8, 256>>>(out, N);
}

// round 9
// speedup vs baseline: 1.4169x; 1.0471x over previous
#include <cuda_runtime.h>
#include <cuda_fp16.h>
#include <cuda_bf16.h>
#include <cuda_fp8.h>
#include <cstdint>

#define NMAX 20000
#define EMAX 320000

__device__ float   g_X[NMAX * 512];      // fp32 X[n][h*128+o] (head-mean)
__device__ uint8_t g_Xf8[NMAX * 512];    // e4m3 (x*32) copy for gathers
__device__ float   g_sprm[NMAX * 8];     // [n*8+h]=s_src, [n*8+4+h]=s_dst
__device__ float   g_sc[EMAX * 4];       // exp(score), slot-major float4
__device__ int2    g_perm[EMAX];         // sorted-by-src {src, dst}
__device__ int     g_cnt[NMAX];          // histogram -> cursor
__device__ int     g_start[NMAX + 1];    // bucket starts
__device__ int     g_bsum[128];          // per-block sums for scan
__device__ float   g_hsum[4];
__device__ int     g_is64;

// ---------------------------------------------------------------------------
__device__ __forceinline__ uint32_t smem_u32(const void* p) {
    uint32_t a;
    asm("{ .reg .u64 t; cvta.to.shared.u64 t, %1; cvt.u32.u64 %0, t; }"
        : "=r"(a) : "l"(p));
    return a;
}

#define LDSM4(r, a)                                                            \
    asm volatile("ldmatrix.sync.aligned.m8n8.x4.shared.b16 {%0,%1,%2,%3}, [%4];" \
        : "=r"((r)[0]), "=r"((r)[1]), "=r"((r)[2]), "=r"((r)[3]) : "r"(a))

#define MMA16816(d, a, b0, b1)                                                 \
    asm volatile("mma.sync.aligned.m16n8k16.row.col.f32.bf16.bf16.f32 "        \
        "{%0,%1,%2,%3}, {%4,%5,%6,%7}, {%8,%9}, {%0,%1,%2,%3};"                \
        : "+f"((d)[0]), "+f"((d)[1]), "+f"((d)[2]), "+f"((d)[3])               \
        : "r"((a)[0]), "r"((a)[1]), "r"((a)[2]), "r"((a)[3]), "r"(b0), "r"(b1))

#define TS       136
#define SM_AV    0
#define SM_AHI   1024
#define SM_ALO   (1024 + 34816)
#define SM_BHI   (35840 + 34816)
#define SM_BLO   (70656 + 34816)
#define K1_SMEM  140288
#define SM_STAGE 1024
#define SSTR     132

// ---------------------------------------------------------------------------
__device__ __forceinline__ void load_edge(const void* edges, int e, int is64,
                                          int& src, int& dst) {
    if (is64) {
        const long long* p = (const long long*)edges;
        src = (int)p[3 * e];
        dst = (int)p[3 * e + 2];
    } else {
        const int* p = (const int*)edges;
        src = p[3 * e];
        dst = p[3 * e + 2];
    }
}

// kzero + int64-vs-int32 detect fused
__global__ void kzero(const unsigned int* e32, int N) {
    int i = blockIdx.x * blockDim.x + threadIdx.x;
    if (i < N) g_cnt[i] = 0;
    if (i < 4) g_hsum[i] = 0.f;
    if (blockIdx.x == 0 && threadIdx.x == 0) {
        int is64 = 1;
        #pragma unroll 1
        for (int j = 0; j < 32; j++) {
            if (e32[2 * j + 1] != 0u) { is64 = 0; break; }
        }
        g_is64 = is64;
    }
}

__global__ void ksortA(const void* __restrict__ edges, int E) {
    int e = blockIdx.x * blockDim.x + threadIdx.x;
    if (e >= E) return;
    int src, dst;
    load_edge(edges, e, g_is64, src, dst);
    atomicAdd(&g_cnt[src], 1);
}

__global__ __launch_bounds__(256) void kscan1(int N) {
    __shared__ int ws[8];
    int i = blockIdx.x * 256 + threadIdx.x;
    int lane = threadIdx.x & 31, wid = threadIdx.x >> 5;
    int v = (i < N) ? g_cnt[i] : 0;
    int x = v;
    #pragma unroll
    for (int off = 16; off > 0; off >>= 1)
        x += __shfl_xor_sync(0xffffffffu, x, off);
    if (lane == 0) ws[wid] = x;
    __syncthreads();
    if (threadIdx.x == 0) {
        int s = 0;
        #pragma unroll
        for (int w = 0; w < 8; w++) s += ws[w];
        g_bsum[blockIdx.x] = s;
    }
}

__global__ __launch_bounds__(128) void kscan2(int nb, int N, int E) {
    __shared__ int sh[128];
    int t = threadIdx.x;
    int v = (t < nb) ? g_bsum[t] : 0;
    sh[t] = v;
    __syncthreads();
    #pragma unroll
    for (int off = 1; off < 128; off <<= 1) {
        int tv = (t >= off) ? sh[t - off] : 0;
        __syncthreads();
        sh[t] += tv;
        __syncthreads();
    }
    if (t < nb) g_bsum[t] = sh[t] - v;
    if (t == 0) g_start[N] = E;
}

__global__ __launch_bounds__(256) void kscan3(int N) {
    __shared__ int ws[8];
    int i = blockIdx.x * 256 + threadIdx.x;
    int lane = threadIdx.x & 31, wid = threadIdx.x >> 5;
    int v = (i < N) ? g_cnt[i] : 0;
    int x = v;
    #pragma unroll
    for (int off = 1; off < 32; off <<= 1) {
        int t = __shfl_up_sync(0xffffffffu, x, off);
        if (lane >= off) x += t;
    }
    if (lane == 31) ws[wid] = x;
    __syncthreads();
    if (wid == 0 && lane < 8) {
        int y = ws[lane];
        #pragma unroll
        for (int off = 1; off < 8; off <<= 1) {
            int t = __shfl_up_sync(0xffu, y, off);
            if (lane >= off) y += t;
        }
        ws[lane] = y;
    }
    __syncthreads();
    int excl = x - v + (wid > 0 ? ws[wid - 1] : 0) + g_bsum[blockIdx.x];
    if (i < N) {
        g_start[i] = excl;
        g_cnt[i]   = excl;
    }
}

__global__ void ksortC(const void* __restrict__ edges, int E) {
    int e = blockIdx.x * blockDim.x + threadIdx.x;
    if (e >= E) return;
    int src, dst;
    load_edge(edges, e, g_is64, src, dst);
    int pos = atomicAdd(&g_cnt[src], 1);
    g_perm[pos] = make_int2(src, dst);
}

// ---------------------------------------------------------------------------
__device__ __forceinline__ void split_pack(float x, float y,
                                           uint32_t& hi, uint32_t& lo) {
    __nv_bfloat16 hx = __float2bfloat16(x), hy = __float2bfloat16(y);
    __nv_bfloat16 lx = __float2bfloat16(x - __bfloat162float(hx));
    __nv_bfloat16 ly = __float2bfloat16(y - __bfloat162float(hy));
    hi = ((uint32_t)*(unsigned short*)&hy << 16) | *(unsigned short*)&hx;
    lo = ((uint32_t)*(unsigned short*)&ly << 16) | *(unsigned short*)&lx;
}

// K1: HMMA bf16-split GEMM. CTA: 128 nodes x 128 cols (head = blockIdx.y).
__global__ __launch_bounds__(256) void k1_mma(const float* __restrict__ A,
                                              const float* __restrict__ Wt,
                                              const float* __restrict__ av,
                                              int N) {
    extern __shared__ char smem[];
    const uint32_t sbase = smem_u32(smem);
    const int h   = blockIdx.y;
    const int nb  = blockIdx.x * 128;
    const int tid = threadIdx.x;
    const int lane = tid & 31, wid = tid >> 5;

    float* sAv = (float*)(smem + SM_AV);
    if (tid < 256) sAv[tid] = av[h * 256 + tid];

    #pragma unroll
    for (int it = 0; it < 16; it++) {
        int g = it * 256 + tid;
        int row = g >> 5;
        int kq  = (g & 31) << 2;
        int n = nb + row;
        float4 v = make_float4(0.f, 0.f, 0.f, 0.f);
        if (n < N) v = *(const float4*)(A + (size_t)n * 128 + kq);
        uint32_t h0, l0, h1, l1;
        split_pack(v.x, v.y, h0, l0);
        split_pack(v.z, v.w, h1, l1);
        uint32_t off = (row * TS + kq) * 2;
        *(uint2*)(smem + SM_AHI + off) = make_uint2(h0, h1);
        *(uint2*)(smem + SM_ALO + off) = make_uint2(l0, l1);
    }
    #pragma unroll
    for (int it = 0; it < 16; it++) {
        int g = it * 256 + tid;
        int row = g >> 5;
        int kq  = (g & 31) << 2;
        float4 v = *(const float4*)(Wt + (size_t)(h * 128 + row) * 128 + kq);
        uint32_t h0, l0, h1, l1;
        split_pack(v.x, v.y, h0, l0);
        split_pack(v.z, v.w, h1, l1);
        uint32_t off = (row * TS + kq) * 2;
        *(uint2*)(smem + SM_BHI + off) = make_uint2(h0, h1);
        *(uint2*)(smem + SM_BLO + off) = make_uint2(l0, l1);
    }
    __syncthreads();

    const int m0 = (wid & 1) * 64;
    const int n0 = (wid >> 1) * 32;

    uint32_t offA[4], offB[2];
    {
        int rowA = m0 + (lane & 15);
        int colA = (lane >> 4) << 3;
        #pragma unroll
        for (int mi = 0; mi < 4; mi++)
            offA[mi] = ((rowA + mi * 16) * TS + colA) * 2;
        int nB = n0 + (lane & 7) + ((lane >> 4) << 3);
        int kB = ((lane >> 3) & 1) << 3;
        #pragma unroll
        for (int nbi = 0; nbi < 2; nbi++)
            offB[nbi] = ((nB + nbi * 16) * TS + kB) * 2;
    }

    float acc[4][4][4];
    #pragma unroll
    for (int mi = 0; mi < 4; mi++)
        #pragma unroll
        for (int ni = 0; ni < 4; ni++)
            #pragma unroll
            for (int q = 0; q < 4; q++) acc[mi][ni][q] = 0.f;

    const uint32_t aHi = sbase + SM_AHI, aLo = sbase + SM_ALO;
    const uint32_t bHi = sbase + SM_BHI, bLo = sbase + SM_BLO;

    #pragma unroll
    for (int ks = 0; ks < 8; ks++) {
        uint32_t AH[4][4], AL[4][4], BH[2][4], BL[2][4];
        #pragma unroll
        for (int mi = 0; mi < 4; mi++) {
            LDSM4(AH[mi], aHi + offA[mi] + ks * 32);
            LDSM4(AL[mi], aLo + offA[mi] + ks * 32);
        }
        #pragma unroll
        for (int nbi = 0; nbi < 2; nbi++) {
            LDSM4(BH[nbi], bHi + offB[nbi] + ks * 32);
            LDSM4(BL[nbi], bLo + offB[nbi] + ks * 32);
        }
        #pragma unroll
        for (int mi = 0; mi < 4; mi++)
            #pragma unroll
            for (int ni = 0; ni < 4; ni++) {
                int gsel = ni >> 1, p = (ni & 1) * 2;
                MMA16816(acc[mi][ni], AH[mi], BH[gsel][p], BH[gsel][p + 1]);
                MMA16816(acc[mi][ni], AH[mi], BL[gsel][p], BL[gsel][p + 1]);
                MMA16816(acc[mi][ni], AL[mi], BH[gsel][p], BH[gsel][p + 1]);
            }
    }

    __syncthreads();

    float* stage = (float*)(smem + SM_STAGE);
    {
        int r = m0 + (lane >> 2);
        int c = n0 + 2 * (lane & 3);
        #pragma unroll
        for (int mi = 0; mi < 4; mi++)
            #pragma unroll
            for (int ni = 0; ni < 4; ni++) {
                int rr = r + mi * 16, cc = c + ni * 8;
                *(float2*)&stage[rr * SSTR + cc] =
                    make_float2(acc[mi][ni][0], acc[mi][ni][1]);
                *(float2*)&stage[(rr + 8) * SSTR + cc] =
                    make_float2(acc[mi][ni][2], acc[mi][ni][3]);
            }
    }
    __syncthreads();

    if (tid < 128) {
        int n = nb + tid;
        if (n < N) {
            float s = 0.f, d = 0.f;
            #pragma unroll
            for (int j = 0; j < 32; j++) {
                float4 xv = *(float4*)&stage[tid * SSTR + j * 4];
                float4 as = *(float4*)&sAv[j * 4];
                float4 ad = *(float4*)&sAv[128 + j * 4];
                s = fmaf(xv.x, as.x, fmaf(xv.y, as.y,
                    fmaf(xv.z, as.z, fmaf(xv.w, as.w, s))));
                d = fmaf(xv.x, ad.x, fmaf(xv.y, ad.y,
                    fmaf(xv.z, ad.z, fmaf(xv.w, ad.w, d))));
            }
            g_sprm[n * 8 + h]     = s;
            g_sprm[n * 8 + 4 + h] = d;
        }
    }

    // X fp32 + e4m3(x*32) writes, both coalesced
    #pragma unroll
    for (int rr = 0; rr < 16; rr++) {
        int row = (tid >> 5) * 16 + rr;
        int n = nb + row;
        if (n < N) {
            float4 v = *(float4*)&stage[row * SSTR + lane * 4];
            size_t off = (size_t)n * 512 + h * 128 + lane * 4;
            *(float4*)(g_X + off) = v;
            __nv_fp8x2_storage_t p0 = __nv_cvt_float2_to_fp8x2(
                make_float2(v.x * 32.f, v.y * 32.f), __NV_SATFINITE, __NV_E4M3);
            __nv_fp8x2_storage_t p1 = __nv_cvt_float2_to_fp8x2(
                make_float2(v.z * 32.f, v.w * 32.f), __NV_SATFINITE, __NV_E4M3);
            uint32_t pk = (uint32_t)p0 | ((uint32_t)p1 << 16);
            *(uint32_t*)(g_Xf8 + off) = pk;
        }
    }
}

// ---------------------------------------------------------------------------
__global__ __launch_bounds__(256) void k3_scores(int E) {
    __shared__ float wsum[8][4];
    int i = blockIdx.x * blockDim.x + threadIdx.x;
    int lane = threadIdx.x & 31, wid = threadIdx.x >> 5;

    float lp[4] = {0.f, 0.f, 0.f, 0.f};
    if (i < E) {
        int2 sd = g_perm[i];
        float4 sv = *(const float4*)(g_sprm + sd.x * 8);
        float4 dv = *(const float4*)(g_sprm + sd.y * 8 + 4);
        float s0 = sv.x + dv.x, s1 = sv.y + dv.y;
        float s2 = sv.z + dv.z, s3 = sv.w + dv.w;
        s0 = s0 > 0.f ? s0 : 0.01f * s0;
        s1 = s1 > 0.f ? s1 : 0.01f * s1;
        s2 = s2 > 0.f ? s2 : 0.01f * s2;
        s3 = s3 > 0.f ? s3 : 0.01f * s3;
        float4 p4 = make_float4(__expf(s0), __expf(s1), __expf(s2), __expf(s3));
        *(float4*)(g_sc + i * 4) = p4;
        lp[0] = p4.x; lp[1] = p4.y; lp[2] = p4.z; lp[3] = p4.w;
    }
    #pragma unroll
    for (int h = 0; h < 4; h++)
        #pragma unroll
        for (int off = 16; off > 0; off >>= 1)
            lp[h] += __shfl_xor_sync(0xffffffffu, lp[h], off);
    if (lane < 4) wsum[wid][lane] = lp[lane];
    __syncthreads();
    if (threadIdx.x < 4) {
        float s = 0.f;
        #pragma unroll
        for (int w = 0; w < 8; w++) s += wsum[w][threadIdx.x];
        atomicAdd(&g_hsum[threadIdx.x], s);
    }
}

// ---------------------------------------------------------------------------
// K5: warp-per-node; fp8 gather (512B/edge); fused head-mean; single store.
__global__ __launch_bounds__(256) void k5_agg(float* __restrict__ out, int N) {
    __shared__ float invZ[4];
    if (threadIdx.x < 4)
        invZ[threadIdx.x] = 0.25f / g_hsum[threadIdx.x] * (1.f / 32.f);
    __syncthreads();

    int lane = threadIdx.x & 31;
    int n = blockIdx.x * 8 + (threadIdx.x >> 5);
    if (n >= N) return;

    int s = g_start[n], eend = g_start[n + 1];
    float4 acc = make_float4(0.f, 0.f, 0.f, 0.f);

    for (int i = s; i < eend; i++) {
        int dst = g_perm[i].y;
        float4 wv = *(const float4*)(g_sc + i * 4);
        float w[4] = {wv.x * invZ[0], wv.y * invZ[1],
                      wv.z * invZ[2], wv.w * invZ[3]};
        const uint8_t* xp = g_Xf8 + (size_t)dst * 512;
        #pragma unroll
        for (int h = 0; h < 4; h++) {
            uint32_t raw = *(const uint32_t*)(xp + h * 128 + lane * 4);
            __half2_raw r0 = __nv_cvt_fp8x2_to_halfraw2(
                (__nv_fp8x2_storage_t)(raw & 0xffff), __NV_E4M3);
            __half2_raw r1 = __nv_cvt_fp8x2_to_halfraw2(
                (__nv_fp8x2_storage_t)(raw >> 16), __NV_E4M3);
            float2 f0 = __half22float2(*(__half2*)&r0);
            float2 f1 = __half22float2(*(__half2*)&r1);
            acc.x = fmaf(w[h], f0.x, acc.x);
            acc.y = fmaf(w[h], f0.y, acc.y);
            acc.z = fmaf(w[h], f1.x, acc.z);
            acc.w = fmaf(w[h], f1.y, acc.w);
        }
    }

    const float4* xv = (const float4*)g_X + (size_t)n * 128;
    float4 m0 = xv[lane], m1 = xv[32 + lane], m2 = xv[64 + lane], m3 = xv[96 + lane];
    float4 r;
    r.x = fmaf(0.25f, m0.x + m1.x + m2.x + m3.x, acc.x);
    r.y = fmaf(0.25f, m0.y + m1.y + m2.y + m3.y, acc.y);
    r.z = fmaf(0.25f, m0.z + m1.z + m2.z + m3.z, acc.z);
    r.w = fmaf(0.25f, m0.w + m1.w + m2.w + m3.w, acc.w);
    ((float4*)out)[(size_t)n * 32 + lane] = r;
}

// ---------------------------------------------------------------------------
extern "C" void kernel_launch(void* const* d_in, const int* in_sizes, int n_in,
                              void* d_out, int out_size) {
    const float* input_h = (const float*)d_in[0];
    const void*  edges   = d_in[1];
    const float* W       = (const float*)d_in[2];
    const float* a       = (const float*)d_in[3];
    float* out = (float*)d_out;

    int N = in_sizes[0] / 128;   // 20000
    int E = in_sizes[1] / 3;     // 320000
    int nb = (N + 255) / 256;

    cudaFuncSetAttribute(k1_mma, cudaFuncAttributeMaxDynamicSharedMemorySize,
                         K1_SMEM);

    kzero<<<nb, 256>>>((const unsigned int*)edges, N);
    ksortA<<<(E + 255) / 256, 256>>>(edges, E);
    kscan1<<<nb, 256>>>(N);
    kscan2<<<1, 128>>>(nb, N, E);
    kscan3<<<nb, 256>>>(N);
    ksortC<<<(E + 255) / 256, 256>>>(edges, E);

    dim3 g1((N + 127) / 128, 4);
    k1_mma<<<g1, 256, K1_SMEM>>>(input_h, W, a, N);

    k3_scores<<<(E + 255) / 256, 256>>>(E);

    k5_agg<<<(N + 7) / 8, 256>>>(out, N);
}